// round 13
// baseline (speedup 1.0000x reference)
#include <cuda_runtime.h>
#include <cuda_bf16.h>
#include <cstddef>
#include <cstdint>

#define NN     3072
#define IND    128
#define HEADS  4
#define ODIM   64
#define EDIM   8
#define HD     256        // HEADS*ODIM
#define TI     32         // i-rows per block
#define JC     16         // j per chunk
#define WROW   17         // w row stride (floats): bank-clean
#define JSPLIT 8
#define JRANGE (NN / JSPLIT)   // 384
#define NCHUNK (JRANGE / JC)   // 24

typedef unsigned long long u64;

// ---------------- scratch (static device globals: no runtime allocs) -------
__device__ __align__(256) float  g_h[NN * HD];                 // 3 MB
__device__ __align__(256) float4 g_ssrc[NN];
__device__ __align__(256) float4 g_sdst[NN];
__device__ __align__(256) float  g_pacc[JSPLIT][NN * HD];      // 25.2 MB
__device__ __align__(256) float  g_pden[JSPLIT][NN * HEADS];

// ---------------- packed fp32x2 + cp.async helpers -------------------------
__device__ __forceinline__ void ffma2(u64& d, u64 a, u64 b) {
    asm("fma.rn.f32x2 %0, %1, %2, %3;" : "=l"(d) : "l"(a), "l"(b), "l"(d));
}
__device__ __forceinline__ u64 pack2(float x) {
    u64 r; asm("mov.b64 %0, {%1, %1};" : "=l"(r) : "f"(x)); return r;
}
__device__ __forceinline__ void cpa16(uint32_t s, const void* g) {
    asm volatile("cp.async.cg.shared.global [%0], [%1], 16;" :: "r"(s), "l"(g));
}
#define CP_COMMIT() asm volatile("cp.async.commit_group;")
#define CP_WAIT0()  asm volatile("cp.async.wait_group 0;" ::: "memory")

// ---------------- dynamic smem layout for k_attn ---------------------------
struct __align__(16) SmemAttn {
    float  ef[TI][JC * EDIM];      // 16 KB : edge_feats tile (single buffer)
    float  hs[JC * HD];            // 16 KB : h tile (single buffer, permuted)
    int    adjb[TI][JC];           // 2 KB  : adjacency tile
    float  w[HEADS][TI * WROW + 8];// 8.8 KB: attention weights
    float4 sdst[JC];               // 256 B : per-chunk s_dst (cp.async staged)
    float4 ssrc[TI];               // 512 B
    float4 epw[EDIM];
    float4 epb;
};                                 // ~44 KB -> 3 blocks/SM

// ---------------- kernel 1: h = x @ W  (3072x128 @ 128x256) ---------------
__global__ __launch_bounds__(256) void k_proj(const float* __restrict__ x,
                                              const float* __restrict__ W) {
    __shared__ float4 xs4[16 * IND / 4];
    const int t  = threadIdx.x;
    const int i0 = blockIdx.x * 16;

    const float4* xg4 = (const float4*)(x + (size_t)i0 * IND);
#pragma unroll
    for (int k = 0; k < 2; k++) xs4[t + 256 * k] = xg4[t + 256 * k];
    __syncthreads();

    float acc[16];
#pragma unroll
    for (int r = 0; r < 16; r++) acc[r] = 0.f;

    for (int k4 = 0; k4 < IND / 4; k4++) {
        const float w0 = W[(k4 * 4 + 0) * HD + t];
        const float w1 = W[(k4 * 4 + 1) * HD + t];
        const float w2 = W[(k4 * 4 + 2) * HD + t];
        const float w3 = W[(k4 * 4 + 3) * HD + t];
#pragma unroll
        for (int r = 0; r < 16; r++) {
            const float4 xv = xs4[r * (IND / 4) + k4];
            acc[r] += xv.x * w0 + xv.y * w1 + xv.z * w2 + xv.w * w3;
        }
    }
#pragma unroll
    for (int r = 0; r < 16; r++) g_h[(size_t)(i0 + r) * HD + t] = acc[r];
}

// ---------------- kernel 2: s_src / s_dst ---------------------------------
__global__ __launch_bounds__(256) void k_scores(const float* __restrict__ a_src,
                                                const float* __restrict__ a_dst) {
    const int tid = blockIdx.x * blockDim.x + threadIdx.x;
    const int n = tid >> 2, h = tid & 3;
    const float4* hv = (const float4*)(g_h + (size_t)n * HD + h * ODIM);
    const float4* as = (const float4*)(a_src + h * ODIM);
    const float4* ad = (const float4*)(a_dst + h * ODIM);
    float ss = 0.f, sd = 0.f;
#pragma unroll
    for (int q = 0; q < ODIM / 4; q++) {
        const float4 hq = hv[q], aq = as[q], dq = ad[q];
        ss += hq.x * aq.x + hq.y * aq.y + hq.z * aq.z + hq.w * aq.w;
        sd += hq.x * dq.x + hq.y * dq.y + hq.z * dq.z + hq.w * dq.w;
    }
    ((float*)g_ssrc)[tid] = ss;
    ((float*)g_sdst)[tid] = sd;
}

// ---------------- prefetch helpers (cp.async) ------------------------------
// ef + adj + sdst tile for the chunk starting at j0 (single buffers).
__device__ __forceinline__ void prefetch_ef(SmemAttn* S, int i0, int j0,
                                            const float* __restrict__ ef,
                                            const int*   __restrict__ adj, int t) {
    // ef tile: 32 rows x 512B = 1024 x 16B units
#pragma unroll
    for (int k = 0; k < 4; k++) {
        const int u  = t + k * 256;
        const int i  = u >> 5;             // 32 units per row
        const int uo = u & 31;
        const uint32_t dst = (uint32_t)__cvta_generic_to_shared(&S->ef[i][uo * 4]);
        cpa16(dst, ef + ((size_t)(i0 + i) * NN + j0) * EDIM + uo * 4);
    }
    // adj tile: 32 x 16 ints = 128 x 16B units
    if (t < 128) {
        const int i  = t >> 2;
        const int j4 = t & 3;
        const uint32_t dst = (uint32_t)__cvta_generic_to_shared(&S->adjb[i][j4 * 4]);
        cpa16(dst, adj + (size_t)(i0 + i) * NN + j0 + j4 * 4);
    }
    // sdst tile: 16 x 16B
    if (t < JC) {
        const uint32_t dst = (uint32_t)__cvta_generic_to_shared(&S->sdst[t]);
        cpa16(dst, g_sdst + j0 + t);
    }
}

// h tile, per-head 16B-chunk permutation: chunk k16 -> (k16&1)*8+(k16>>1)
// so phase-2's p0/p1 halves are contiguous 128B each.
__device__ __forceinline__ void prefetch_h(SmemAttn* S, int j0, int t) {
#pragma unroll
    for (int k = 0; k < 4; k++) {
        const int u   = t + k * 256;
        const int row = u >> 6;            // 64 x 16B units per j-row
        const int cu  = u & 63;
        const int h2  = cu >> 4;
        const int k16 = cu & 15;
        const int pos = (k16 & 1) * 8 + (k16 >> 1);
        const uint32_t dst = (uint32_t)__cvta_generic_to_shared(
            &S->hs[row * HD + h2 * ODIM + pos * 4]);
        cpa16(dst, g_h + (size_t)(j0 + row) * HD + cu * 4);
    }
}

// ---------------- kernel 3: fused attention, occ-3, audited registers ------
__global__ __launch_bounds__(256, 3) void k_attn(const float* __restrict__ ef,
                                                 const int*   __restrict__ adj,
                                                 const float* __restrict__ ep_w,
                                                 const float* __restrict__ ep_b) {
    extern __shared__ char smem_raw[];
    SmemAttn* S = (SmemAttn*)smem_raw;

    const int t     = threadIdx.x;
    const int i0    = blockIdx.x * TI;
    const int js    = blockIdx.y;
    const int jbase = js * JRANGE;

    if (t < EDIM) S->epw[t] = ((const float4*)ep_w)[t];
    if (t == EDIM) S->epb = *(const float4*)ep_b;
    if (t < TI) S->ssrc[t] = g_ssrc[i0 + t];

    prefetch_ef(S, i0, jbase, ef, adj, t);   // ef(0)+adj(0)+sdst(0)
    CP_COMMIT();

    // phase-2 identity: per head a 32x64 C tile, 4 rows x 8 cols per thread
    const int h2  = t >> 6;
    const int s2  = t & 63;
    const int il0 = (s2 >> 3) * 4;     // 0,4,...,28
    const int d8  = s2 & 7;            // d0 = d8*8
    // phase-1 identity: 16 j-lanes x 16 i-groups, 2 passes
    const int jl  = t & 15;
    const int ih  = t >> 4;

    u64 acc2[4][4];                    // 32 regs
#pragma unroll
    for (int r = 0; r < 4; r++)
#pragma unroll
        for (int q = 0; q < 4; q++) acc2[r][q] = 0ull;
    float pden[4];                     // denominator, accumulated in phase-2
#pragma unroll
    for (int r = 0; r < 4; r++) pden[r] = 0.f;

    for (int c = 0; c < NCHUNK; c++) {
        const int j0 = jbase + c * JC;

        CP_WAIT0();          // ef(c): issued during phase-2(c-1)
        __syncthreads();     // syncA: ef visible; phase-2(c-1) readers done

        prefetch_h(S, j0, t);   // h(c): lands during phase-1
        CP_COMMIT();

        // ---- phase 1: w = adj ? exp(leaky(ssrc+sdst+edge@epw+epb)) : 0
#pragma unroll 1
        for (int p = 0; p < 2; p++) {
            const int i  = p * 16 + ih;
            const float4 ea = *(const float4*)&S->ef[i][jl * 8];
            const float4 eb = *(const float4*)&S->ef[i][jl * 8 + 4];
            const int    am = S->adjb[i][jl];
            const float4 ss4 = S->ssrc[i];
            const float4 sd4 = S->sdst[jl];
            const float4 epb4 = S->epb;

            float vx = epb4.x + ss4.x + sd4.x;
            float vy = epb4.y + ss4.y + sd4.y;
            float vz = epb4.z + ss4.z + sd4.z;
            float vw = epb4.w + ss4.w + sd4.w;
            float4 we;
            we = S->epw[0]; vx += ea.x * we.x; vy += ea.x * we.y; vz += ea.x * we.z; vw += ea.x * we.w;
            we = S->epw[1]; vx += ea.y * we.x; vy += ea.y * we.y; vz += ea.y * we.z; vw += ea.y * we.w;
            we = S->epw[2]; vx += ea.z * we.x; vy += ea.z * we.y; vz += ea.z * we.z; vw += ea.z * we.w;
            we = S->epw[3]; vx += ea.w * we.x; vy += ea.w * we.y; vz += ea.w * we.z; vw += ea.w * we.w;
            we = S->epw[4]; vx += eb.x * we.x; vy += eb.x * we.y; vz += eb.x * we.z; vw += eb.x * we.w;
            we = S->epw[5]; vx += eb.y * we.x; vy += eb.y * we.y; vz += eb.y * we.z; vw += eb.y * we.w;
            we = S->epw[6]; vx += eb.z * we.x; vy += eb.z * we.y; vz += eb.z * we.z; vw += eb.z * we.w;
            we = S->epw[7]; vx += eb.w * we.x; vy += eb.w * we.y; vz += eb.w * we.z; vw += eb.w * we.w;

            vx = fmaxf(vx, 0.2f * vx);
            vy = fmaxf(vy, 0.2f * vy);
            vz = fmaxf(vz, 0.2f * vz);
            vw = fmaxf(vw, 0.2f * vw);

            S->w[0][i * WROW + jl] = am ? __expf(vx) : 0.f;
            S->w[1][i * WROW + jl] = am ? __expf(vy) : 0.f;
            S->w[2][i * WROW + jl] = am ? __expf(vz) : 0.f;
            S->w[3][i * WROW + jl] = am ? __expf(vw) : 0.f;
        }

        CP_WAIT0();          // h(c) complete
        __syncthreads();     // syncB: w + h visible to all

        if (c + 1 < NCHUNK) {          // ef(c+1): covered by phase-2 (R8-proven)
            prefetch_ef(S, i0, j0 + JC, ef, adj, t);
            CP_COMMIT();
        }

        // ---- phase 2: acc[i,d] += w[i,j] * h[j,h2,d]; d8==0 lanes also
        //      accumulate the softmax denominator (they read every w anyway).
        const float* wbase = &S->w[h2][il0 * WROW];
        const float* hbase = &S->hs[h2 * ODIM + d8 * 4];
#pragma unroll 2
        for (int j = 0; j < JC; j++) {
            const ulonglong2* hb = (const ulonglong2*)(hbase + j * HD);
            const ulonglong2 p0 = hb[0];
            const ulonglong2 p1 = hb[8];   // +128B (odd-chunk half)
#pragma unroll
            for (int r = 0; r < 4; r++) {
                const float wv = wbase[r * WROW + j];
                if (d8 == 0) pden[r] += wv;
                const u64 wp = pack2(wv);
                ffma2(acc2[r][0], wp, p0.x); ffma2(acc2[r][1], wp, p0.y);
                ffma2(acc2[r][2], wp, p1.x); ffma2(acc2[r][3], wp, p1.y);
            }
        }
        // no trailing barrier: w/h rewritten only after next syncA/syncB.
    }

    // ---- write additive partials (packed)
    float* pa = g_pacc[js];
#pragma unroll
    for (int r = 0; r < 4; r++) {
        ulonglong2* dst =
            (ulonglong2*)(pa + (size_t)(i0 + il0 + r) * HD + h2 * ODIM + d8 * 8);
        ulonglong2 o0; o0.x = acc2[r][0]; o0.y = acc2[r][1];
        ulonglong2 o1; o1.x = acc2[r][2]; o1.y = acc2[r][3];
        dst[0] = o0;
        dst[1] = o1;
    }
    // denominator: d8==0 threads hold the full j-sum for (il0..il0+3, h2)
    if (d8 == 0) {
#pragma unroll
        for (int r = 0; r < 4; r++)
            g_pden[js][(i0 + il0 + r) * HEADS + h2] = pden[r];
    }
}

// ---------------- kernel 4: combine + normalize + layernorm ----------------
__global__ __launch_bounds__(256) void k_final(const float* __restrict__ gamma,
                                               const float* __restrict__ beta,
                                               float* __restrict__ out) {
    __shared__ float rs[4][2], rq[4][2];
    __shared__ float mean_s[4], rstd_s[4];

    const int t = threadIdx.x;
    const int r = t >> 6;
    const int s = t & 63;
    const int n = blockIdx.x * 4 + r;

    float4 v = make_float4(0.f, 0.f, 0.f, 0.f);
#pragma unroll
    for (int sp = 0; sp < JSPLIT; sp++) {
        const float4 p = *(const float4*)&g_pacc[sp][(size_t)n * HD + s * 4];
        v.x += p.x; v.y += p.y; v.z += p.z; v.w += p.w;
    }
    const int h = s >> 4;
    float den = 0.f;
#pragma unroll
    for (int sp = 0; sp < JSPLIT; sp++) den += g_pden[sp][n * HEADS + h];
    const float inv = __frcp_rn(den);
    v.x *= inv; v.y *= inv; v.z *= inv; v.w *= inv;

    float sum = v.x + v.y + v.z + v.w;
    float sq  = v.x * v.x + v.y * v.y + v.z * v.z + v.w * v.w;
#pragma unroll
    for (int o = 16; o; o >>= 1) {
        sum += __shfl_xor_sync(0xffffffffu, sum, o);
        sq  += __shfl_xor_sync(0xffffffffu, sq, o);
    }
    const int half = (t >> 5) & 1;
    if ((t & 31) == 0) { rs[r][half] = sum; rq[r][half] = sq; }
    __syncthreads();
    if (s == 0) {
        const float S = rs[r][0] + rs[r][1];
        const float Q = rq[r][0] + rq[r][1];
        const float m = S * (1.f / HD);
        const float var = Q * (1.f / HD) - m * m;
        mean_s[r] = m;
        rstd_s[r] = rsqrtf(var + 1e-5f);
    }
    __syncthreads();
    const float m   = mean_s[r];
    const float rsd = rstd_s[r];
    const float4 g = ((const float4*)gamma)[s];
    const float4 b = ((const float4*)beta)[s];
    float4 o;
    o.x = (v.x - m) * rsd * g.x + b.x;
    o.y = (v.y - m) * rsd * g.y + b.y;
    o.z = (v.z - m) * rsd * g.z + b.z;
    o.w = (v.w - m) * rsd * g.w + b.w;
    ((float4*)out)[(size_t)n * (HD / 4) + s] = o;
}

// ---------------- launch ----------------------------------------------------
extern "C" void kernel_launch(void* const* d_in, const int* in_sizes, int n_in,
                              void* d_out, int out_size) {
    const float* x      = (const float*)d_in[0];
    const int*   adj    = (const int*)  d_in[1];
    const float* ef     = (const float*)d_in[2];
    const float* W      = (const float*)d_in[3];
    const float* a_src  = (const float*)d_in[4];
    const float* a_dst  = (const float*)d_in[5];
    const float* ep_w   = (const float*)d_in[6];
    const float* ep_b   = (const float*)d_in[7];
    const float* gamma  = (const float*)d_in[8];
    const float* beta   = (const float*)d_in[9];
    float* out = (float*)d_out;

    const int smem_bytes = (int)sizeof(SmemAttn);   // ~44 KB -> 3 blocks/SM
    cudaFuncSetAttribute(k_attn, cudaFuncAttributeMaxDynamicSharedMemorySize,
                         smem_bytes);

    k_proj  <<<NN / 16, 256>>>(x, W);
    k_scores<<<(NN * HEADS) / 256, 256>>>(a_src, a_dst);
    k_attn  <<<dim3(NN / TI, JSPLIT), 256, smem_bytes>>>(ef, adj, ep_w, ep_b);
    k_final <<<NN / 4, 256>>>(gamma, beta, out);
}

// round 14
// speedup vs baseline: 1.0868x; 1.0868x over previous
#include <cuda_runtime.h>
#include <cuda_bf16.h>
#include <cstddef>
#include <cstdint>

#define NN     3072
#define IND    128
#define HEADS  4
#define ODIM   64
#define EDIM   8
#define HD     256        // HEADS*ODIM
#define TI     64         // i-rows per block
#define JC     16         // j per chunk
#define EFROW  132        // ef row stride (floats): pad for conflict-free LDS.128
#define ADJROW 20         // adj row stride (ints): 80B, 16B-aligned
#define JSPLIT 6
#define JRANGE (NN / JSPLIT)   // 512
#define NCHUNK (JRANGE / JC)   // 32

typedef unsigned long long u64;

// ---------------- scratch (static device globals: no runtime allocs) -------
__device__ __align__(256) float  g_h[NN * HD];                 // 3 MB
__device__ __align__(256) float4 g_ssrc[NN];
__device__ __align__(256) float4 g_sdst[NN];
__device__ __align__(256) float  g_pacc[JSPLIT][NN * HD];      // 18.9 MB
__device__ __align__(256) float  g_pden[JSPLIT][NN * HEADS];

// ---------------- packed fp32x2 + cp.async helpers -------------------------
__device__ __forceinline__ void ffma2(u64& d, u64 a, u64 b) {
    asm("fma.rn.f32x2 %0, %1, %2, %3;" : "=l"(d) : "l"(a), "l"(b), "l"(d));
}
__device__ __forceinline__ u64 pack2(float x) {
    u64 r; asm("mov.b64 %0, {%1, %1};" : "=l"(r) : "f"(x)); return r;
}
__device__ __forceinline__ void cpa16(uint32_t s, const void* g) {
    asm volatile("cp.async.cg.shared.global [%0], [%1], 16;" :: "r"(s), "l"(g));
}
#define CP_COMMIT() asm volatile("cp.async.commit_group;")
#define CP_WAIT0()  asm volatile("cp.async.wait_group 0;" ::: "memory")

// ---------------- dynamic smem layout for k_attn ---------------------------
struct __align__(16) SmemAttn {
    float  ef[2][TI * EFROW];      // 67.6 KB : edge_feats (double buffer, padded)
    float  hs[2][JC * HD];         // 32 KB   : h tiles (double buffer)
    int    adjb[2][TI * ADJROW];   // 10.2 KB : adjacency (double buffer, padded)
    float4 sdst[2][JC];            // 512 B   : per-chunk s_dst
};                                 // ~110.4 KB -> 2 blocks/SM

// ---------------- kernel 1: h = x @ W  (3072x128 @ 128x256) ---------------
__global__ __launch_bounds__(256) void k_proj(const float* __restrict__ x,
                                              const float* __restrict__ W) {
    __shared__ float4 xs4[16 * IND / 4];
    const int t  = threadIdx.x;
    const int i0 = blockIdx.x * 16;

    const float4* xg4 = (const float4*)(x + (size_t)i0 * IND);
#pragma unroll
    for (int k = 0; k < 2; k++) xs4[t + 256 * k] = xg4[t + 256 * k];
    __syncthreads();

    float acc[16];
#pragma unroll
    for (int r = 0; r < 16; r++) acc[r] = 0.f;

    for (int k4 = 0; k4 < IND / 4; k4++) {
        const float w0 = W[(k4 * 4 + 0) * HD + t];
        const float w1 = W[(k4 * 4 + 1) * HD + t];
        const float w2 = W[(k4 * 4 + 2) * HD + t];
        const float w3 = W[(k4 * 4 + 3) * HD + t];
#pragma unroll
        for (int r = 0; r < 16; r++) {
            const float4 xv = xs4[r * (IND / 4) + k4];
            acc[r] += xv.x * w0 + xv.y * w1 + xv.z * w2 + xv.w * w3;
        }
    }
#pragma unroll
    for (int r = 0; r < 16; r++) g_h[(size_t)(i0 + r) * HD + t] = acc[r];
}

// ---------------- kernel 2: s_src / s_dst ---------------------------------
__global__ __launch_bounds__(256) void k_scores(const float* __restrict__ a_src,
                                                const float* __restrict__ a_dst) {
    const int tid = blockIdx.x * blockDim.x + threadIdx.x;
    const int n = tid >> 2, h = tid & 3;
    const float4* hv = (const float4*)(g_h + (size_t)n * HD + h * ODIM);
    const float4* as = (const float4*)(a_src + h * ODIM);
    const float4* ad = (const float4*)(a_dst + h * ODIM);
    float ss = 0.f, sd = 0.f;
#pragma unroll
    for (int q = 0; q < ODIM / 4; q++) {
        const float4 hq = hv[q], aq = as[q], dq = ad[q];
        ss += hq.x * aq.x + hq.y * aq.y + hq.z * aq.z + hq.w * aq.w;
        sd += hq.x * dq.x + hq.y * dq.y + hq.z * dq.z + hq.w * dq.w;
    }
    ((float*)g_ssrc)[tid] = ss;
    ((float*)g_sdst)[tid] = sd;
}

// ---------------- one-group prefetch of a full chunk -----------------------
__device__ __forceinline__ void prefetch_all(SmemAttn* S, int buf, int i0, int j0,
                                             const float* __restrict__ ef,
                                             const int*   __restrict__ adj, int t) {
    // ef tile: 64 rows x 128 floats (stored stride 132) = 2048 x 16B
#pragma unroll
    for (int k = 0; k < 8; k++) {
        const int u  = t + k * 256;
        const int i  = u >> 5;             // 32 units per row
        const int uo = u & 31;
        const uint32_t dst = (uint32_t)__cvta_generic_to_shared(
            &S->ef[buf][i * EFROW + uo * 4]);
        cpa16(dst, ef + ((size_t)(i0 + i) * NN + j0) * EDIM + uo * 4);
    }
    // adj tile: 64 rows x 16 ints (stored stride 20) = 256 x 16B
    {
        const int i  = t >> 2;
        const int j4 = t & 3;
        const uint32_t dst = (uint32_t)__cvta_generic_to_shared(
            &S->adjb[buf][i * ADJROW + j4 * 4]);
        cpa16(dst, adj + (size_t)(i0 + i) * NN + j0 + j4 * 4);
    }
    // h tile: 16 rows x 256 floats = 1024 x 16B
#pragma unroll
    for (int k = 0; k < 4; k++) {
        const int u   = t + k * 256;
        const int row = u >> 6;
        const int cu  = u & 63;
        const uint32_t dst = (uint32_t)__cvta_generic_to_shared(
            &S->hs[buf][row * HD + cu * 4]);
        cpa16(dst, g_h + (size_t)(j0 + row) * HD + cu * 4);
    }
    // sdst tile: 16 x 16B
    if (t < JC) {
        const uint32_t dst = (uint32_t)__cvta_generic_to_shared(&S->sdst[buf][t]);
        cpa16(dst, g_sdst + j0 + t);
    }
}

// ---------------- kernel 3: fused single-phase attention -------------------
// thread = (i-row, head): computes its head's logit AND accumulates output.
// No w matrix in smem, no transpose, ONE barrier per chunk.
__global__ __launch_bounds__(256, 2) void k_attn(const float* __restrict__ ef,
                                                 const int*   __restrict__ adj,
                                                 const float* __restrict__ ep_w,
                                                 const float* __restrict__ ep_b) {
    extern __shared__ char smem_raw[];
    SmemAttn* S = (SmemAttn*)smem_raw;

    const int t     = threadIdx.x;
    const int h2    = t >> 6;          // head (constant within each warp)
    const int iloc  = t & 63;          // i-row within tile
    const int i0    = blockIdx.x * TI;
    const int js    = blockIdx.y;
    const int jbase = js * JRANGE;
    const int gi    = i0 + iloc;

    // per-thread constants from gmem (once)
    float epwh[EDIM];
#pragma unroll
    for (int e = 0; e < EDIM; e++) epwh[e] = ep_w[e * HEADS + h2];
    const float base0 = ep_b[h2] + ((const float*)g_ssrc)[gi * 4 + h2];

    prefetch_all(S, 0, i0, jbase, ef, adj, t);   // chunk 0
    CP_COMMIT();

    u64 acc[32];                       // 64 regs: d = 0..63 packed
#pragma unroll
    for (int k = 0; k < 32; k++) acc[k] = 0ull;
    float pden = 0.f;

    for (int c = 0; c < NCHUNK; c++) {
        const int buf = c & 1;

        CP_WAIT0();          // chunk c landed (issued a full chunk ago)
        __syncthreads();     // visible to all; all warps done reading buf^1

        if (c + 1 < NCHUNK) {
            prefetch_all(S, buf ^ 1, i0, jbase + (c + 1) * JC, ef, adj, t);
            CP_COMMIT();
        }

        const float* efr = &S->ef[buf][iloc * EFROW];
        const int*   ar  = &S->adjb[buf][iloc * ADJROW];
        const float* sdp = (const float*)&S->sdst[buf][0];
        const float* hp  = &S->hs[buf][h2 * ODIM];

#pragma unroll 2
        for (int j = 0; j < JC; j++) {
            const float4 ea = *(const float4*)(efr + j * 8);
            const float4 eb = *(const float4*)(efr + j * 8 + 4);
            const int    am = ar[j];
            float v = base0 + sdp[j * 4 + h2];          // broadcast LDS
            v += ea.x * epwh[0] + ea.y * epwh[1] + ea.z * epwh[2] + ea.w * epwh[3];
            v += eb.x * epwh[4] + eb.y * epwh[5] + eb.z * epwh[6] + eb.w * epwh[7];
            v = fmaxf(v, 0.2f * v);                     // leaky relu
            const float w = am ? __expf(v) : 0.f;
            pden += w;
            const u64 wp = pack2(w);
            const ulonglong2* hb = (const ulonglong2*)(hp + j * HD);
#pragma unroll
            for (int k = 0; k < 16; k++) {              // broadcast LDS.128
                const ulonglong2 hv = hb[k];
                ffma2(acc[2 * k],     wp, hv.x);
                ffma2(acc[2 * k + 1], wp, hv.y);
            }
        }
        // no second barrier: buf is rewritten only after the next sync.
    }

    // ---- write partials: contiguous 256B per thread + scalar denominator
    {
        ulonglong2* dst =
            (ulonglong2*)(g_pacc[js] + (size_t)gi * HD + h2 * ODIM);
#pragma unroll
        for (int k = 0; k < 16; k++) {
            ulonglong2 o; o.x = acc[2 * k]; o.y = acc[2 * k + 1];
            dst[k] = o;
        }
        g_pden[js][gi * HEADS + h2] = pden;
    }
}

// ---------------- kernel 4: combine + normalize + layernorm ----------------
__global__ __launch_bounds__(256) void k_final(const float* __restrict__ gamma,
                                               const float* __restrict__ beta,
                                               float* __restrict__ out) {
    __shared__ float rs[4][2], rq[4][2];
    __shared__ float mean_s[4], rstd_s[4];

    const int t = threadIdx.x;
    const int r = t >> 6;
    const int s = t & 63;
    const int n = blockIdx.x * 4 + r;

    float4 v = make_float4(0.f, 0.f, 0.f, 0.f);
#pragma unroll
    for (int sp = 0; sp < JSPLIT; sp++) {
        const float4 p = *(const float4*)&g_pacc[sp][(size_t)n * HD + s * 4];
        v.x += p.x; v.y += p.y; v.z += p.z; v.w += p.w;
    }
    const int h = s >> 4;
    float den = 0.f;
#pragma unroll
    for (int sp = 0; sp < JSPLIT; sp++) den += g_pden[sp][n * HEADS + h];
    const float inv = __frcp_rn(den);
    v.x *= inv; v.y *= inv; v.z *= inv; v.w *= inv;

    float sum = v.x + v.y + v.z + v.w;
    float sq  = v.x * v.x + v.y * v.y + v.z * v.z + v.w * v.w;
#pragma unroll
    for (int o = 16; o; o >>= 1) {
        sum += __shfl_xor_sync(0xffffffffu, sum, o);
        sq  += __shfl_xor_sync(0xffffffffu, sq, o);
    }
    const int half = (t >> 5) & 1;
    if ((t & 31) == 0) { rs[r][half] = sum; rq[r][half] = sq; }
    __syncthreads();
    if (s == 0) {
        const float S = rs[r][0] + rs[r][1];
        const float Q = rq[r][0] + rq[r][1];
        const float m = S * (1.f / HD);
        const float var = Q * (1.f / HD) - m * m;
        mean_s[r] = m;
        rstd_s[r] = rsqrtf(var + 1e-5f);
    }
    __syncthreads();
    const float m   = mean_s[r];
    const float rsd = rstd_s[r];
    const float4 g = ((const float4*)gamma)[s];
    const float4 b = ((const float4*)beta)[s];
    float4 o;
    o.x = (v.x - m) * rsd * g.x + b.x;
    o.y = (v.y - m) * rsd * g.y + b.y;
    o.z = (v.z - m) * rsd * g.z + b.z;
    o.w = (v.w - m) * rsd * g.w + b.w;
    ((float4*)out)[(size_t)n * (HD / 4) + s] = o;
}

// ---------------- launch ----------------------------------------------------
extern "C" void kernel_launch(void* const* d_in, const int* in_sizes, int n_in,
                              void* d_out, int out_size) {
    const float* x      = (const float*)d_in[0];
    const int*   adj    = (const int*)  d_in[1];
    const float* ef     = (const float*)d_in[2];
    const float* W      = (const float*)d_in[3];
    const float* a_src  = (const float*)d_in[4];
    const float* a_dst  = (const float*)d_in[5];
    const float* ep_w   = (const float*)d_in[6];
    const float* ep_b   = (const float*)d_in[7];
    const float* gamma  = (const float*)d_in[8];
    const float* beta   = (const float*)d_in[9];
    float* out = (float*)d_out;

    const int smem_bytes = (int)sizeof(SmemAttn);   // ~110.4 KB
    cudaFuncSetAttribute(k_attn, cudaFuncAttributeMaxDynamicSharedMemorySize,
                         smem_bytes);

    k_proj  <<<NN / 16, 256>>>(x, W);
    k_scores<<<(NN * HEADS) / 256, 256>>>(a_src, a_dst);
    k_attn  <<<dim3(NN / TI, JSPLIT), 256, smem_bytes>>>(ef, adj, ep_w, ep_b);
    k_final <<<NN / 4, 256>>>(gamma, beta, out);
}

// round 15
// speedup vs baseline: 1.1386x; 1.0477x over previous
#include <cuda_runtime.h>
#include <cuda_bf16.h>
#include <cstddef>
#include <cstdint>

#define NN     3072
#define IND    128
#define HEADS  4
#define ODIM   64
#define EDIM   8
#define HD     256        // HEADS*ODIM
#define TI     64         // i-rows per block
#define JC     16         // j per chunk
#define WIPAD  66         // w2 row stride per j (f2 units): 64 rows + 2 pad, odd*2
#define JSPLIT 6
#define JRANGE (NN / JSPLIT)   // 512
#define NCHUNK (JRANGE / JC)   // 32

typedef unsigned long long u64;

// ---------------- scratch (static device globals: no runtime allocs) -------
__device__ __align__(256) float  g_h[NN * HD];                 // 3 MB
__device__ __align__(256) float4 g_ssrc[NN];
__device__ __align__(256) float4 g_sdst[NN];
__device__ __align__(256) float  g_pacc[JSPLIT][NN * HD];      // 18.9 MB
__device__ __align__(256) float  g_pden[JSPLIT][NN * HEADS];

// ---------------- packed fp32x2 + cp.async helpers -------------------------
__device__ __forceinline__ void ffma2(u64& d, u64 a, u64 b) {
    asm("fma.rn.f32x2 %0, %1, %2, %3;" : "=l"(d) : "l"(a), "l"(b), "l"(d));
}
__device__ __forceinline__ void cpa16(uint32_t s, const void* g) {
    asm volatile("cp.async.cg.shared.global [%0], [%1], 16;" :: "r"(s), "l"(g));
}
#define CP_COMMIT() asm volatile("cp.async.commit_group;")
#define CP_WAIT0()  asm volatile("cp.async.wait_group 0;" ::: "memory")

// ---------------- dynamic smem layout for k_attn ---------------------------
// w2: attention weights stored PRE-DUPLICATED {w,w} (direct FFMA2 operand via
// LDS.64, no pack MOVs), transposed [j][i'] with i' = (i&7)*8 + (i>>3) so the
// per-warp il0-group addresses land on distinct banks (conflict-free reads).
// WIPAD = 66 f2/j keeps j-rows bank-staggered (66*2 mod 32 = 4).
struct __align__(16) SmemAttn {
    float  ef[TI][JC * EDIM];      // 32 KB : edge_feats tile (single buffer)
    float  hs[JC * HD];            // 16 KB : h tile (single buffer, permuted)
    int    adjb[TI][JC];           // 4 KB  : adjacency tile
    float2 w2[HEADS][JC * WIPAD];  // 33 KB : duplicated attention weights
    float4 sdst[JRANGE];           // 8 KB
    float4 ssrc[TI];               // 1 KB
    float4 epw[EDIM];
    float4 epb;
};                                 // ~94.5 KB -> 2 blocks/SM

// ---------------- kernel 1: h = x @ W  (3072x128 @ 128x256) ---------------
__global__ __launch_bounds__(256) void k_proj(const float* __restrict__ x,
                                              const float* __restrict__ W) {
    __shared__ float4 xs4[16 * IND / 4];
    const int t  = threadIdx.x;
    const int i0 = blockIdx.x * 16;

    const float4* xg4 = (const float4*)(x + (size_t)i0 * IND);
#pragma unroll
    for (int k = 0; k < 2; k++) xs4[t + 256 * k] = xg4[t + 256 * k];
    __syncthreads();

    float acc[16];
#pragma unroll
    for (int r = 0; r < 16; r++) acc[r] = 0.f;

    for (int k4 = 0; k4 < IND / 4; k4++) {
        const float w0 = W[(k4 * 4 + 0) * HD + t];
        const float w1 = W[(k4 * 4 + 1) * HD + t];
        const float w2 = W[(k4 * 4 + 2) * HD + t];
        const float w3 = W[(k4 * 4 + 3) * HD + t];
#pragma unroll
        for (int r = 0; r < 16; r++) {
            const float4 xv = xs4[r * (IND / 4) + k4];
            acc[r] += xv.x * w0 + xv.y * w1 + xv.z * w2 + xv.w * w3;
        }
    }
#pragma unroll
    for (int r = 0; r < 16; r++) g_h[(size_t)(i0 + r) * HD + t] = acc[r];
}

// ---------------- kernel 2: s_src / s_dst ---------------------------------
__global__ __launch_bounds__(256) void k_scores(const float* __restrict__ a_src,
                                                const float* __restrict__ a_dst) {
    const int tid = blockIdx.x * blockDim.x + threadIdx.x;
    const int n = tid >> 2, h = tid & 3;
    const float4* hv = (const float4*)(g_h + (size_t)n * HD + h * ODIM);
    const float4* as = (const float4*)(a_src + h * ODIM);
    const float4* ad = (const float4*)(a_dst + h * ODIM);
    float ss = 0.f, sd = 0.f;
#pragma unroll
    for (int q = 0; q < ODIM / 4; q++) {
        const float4 hq = hv[q], aq = as[q], dq = ad[q];
        ss += hq.x * aq.x + hq.y * aq.y + hq.z * aq.z + hq.w * aq.w;
        sd += hq.x * dq.x + hq.y * dq.y + hq.z * dq.z + hq.w * dq.w;
    }
    ((float*)g_ssrc)[tid] = ss;
    ((float*)g_sdst)[tid] = sd;
}

// ---------------- prefetch helpers (cp.async) ------------------------------
__device__ __forceinline__ void prefetch_ef(SmemAttn* S, int i0, int j0,
                                            const float* __restrict__ ef,
                                            const int*   __restrict__ adj, int t) {
    // ef tile: 64 rows x 512B = 2048 x 16B
#pragma unroll
    for (int k = 0; k < 8; k++) {
        const int u  = t + k * 256;
        const int i  = u >> 5;             // 32 units per row
        const int uo = u & 31;
        const uint32_t dst = (uint32_t)__cvta_generic_to_shared(&S->ef[i][uo * 4]);
        cpa16(dst, ef + ((size_t)(i0 + i) * NN + j0) * EDIM + uo * 4);
    }
    // adj tile: 64 x 16 ints = 256 x 16B
    {
        const int i  = t >> 2;
        const int j4 = t & 3;
        const uint32_t dst = (uint32_t)__cvta_generic_to_shared(&S->adjb[i][j4 * 4]);
        cpa16(dst, adj + (size_t)(i0 + i) * NN + j0 + j4 * 4);
    }
}

// h tile with per-head 16B-chunk permutation: chunk k (0..15) -> (k&1)*8+(k>>1)
// so phase-2's p0 (even chunks) and p1 (odd chunks) are each contiguous 128B.
__device__ __forceinline__ void prefetch_h(SmemAttn* S, int j0, int t) {
#pragma unroll
    for (int k = 0; k < 4; k++) {
        const int u   = t + k * 256;
        const int row = u >> 6;            // 64 units per row (1 KB)
        const int cu  = u & 63;
        const int h2  = cu >> 4;
        const int k16 = cu & 15;
        const int pos = (k16 & 1) * 8 + (k16 >> 1);
        const uint32_t dst = (uint32_t)__cvta_generic_to_shared(
            &S->hs[row * HD + h2 * ODIM + pos * 4]);
        cpa16(dst, g_h + (size_t)(j0 + row) * HD + cu * 4);
    }
}

// ---------------- kernel 3: fused attention, fully smem-staged -------------
__global__ __launch_bounds__(256, 2) void k_attn(const float* __restrict__ ef,
                                                 const int*   __restrict__ adj,
                                                 const float* __restrict__ ep_w,
                                                 const float* __restrict__ ep_b) {
    extern __shared__ char smem_raw[];
    SmemAttn* S = (SmemAttn*)smem_raw;

    const int t     = threadIdx.x;
    const int i0    = blockIdx.x * TI;
    const int js    = blockIdx.y;
    const int jbase = js * JRANGE;

    if (t < EDIM) S->epw[t] = ((const float4*)ep_w)[t];
    if (t == EDIM) S->epb = *(const float4*)ep_b;
    if (t < TI) S->ssrc[t] = g_ssrc[i0 + t];
    for (int k = t; k < JRANGE; k += 256) S->sdst[k] = g_sdst[jbase + k];

    prefetch_ef(S, i0, jbase, ef, adj, t);
    CP_COMMIT();

    // phase-2 identity: per head a 64x64 C tile, 8 rows x 8 cols per thread
    const int h2  = t >> 6;
    const int s2  = t & 63;
    const int gi8 = (s2 >> 3);         // il0 = gi8*8
    const int d8  = (s2 & 7);          // d0 = d8*8
    // phase-1 identity: 16 j-lanes x 16 i-groups, 4 passes
    const int jl  = t & 15;
    const int ih  = t >> 4;

    u64 acc2[8][4];
#pragma unroll
    for (int r = 0; r < 8; r++)
#pragma unroll
        for (int q = 0; q < 4; q++) acc2[r][q] = 0ull;
    float pden[4][4];
#pragma unroll
    for (int p = 0; p < 4; p++)
#pragma unroll
        for (int h = 0; h < 4; h++) pden[p][h] = 0.f;

    for (int c = 0; c < NCHUNK; c++) {
        const int j0 = jbase + c * JC;

        CP_WAIT0();          // ef(c) [and stray h(c-1)] complete
        __syncthreads();     // syncA: ef visible; all phase-2(c-1) readers done

        prefetch_h(S, j0, t);   // safe: h buffer free after syncA
        CP_COMMIT();

        // ---- phase 1: w = adj ? exp(leaky(ssrc+sdst+edge@epw+epb)) : 0
        const float4 epb4 = S->epb;
#pragma unroll
        for (int p = 0; p < 4; p++) {
            const int i  = p * 16 + ih;
            const float4 ea = *(const float4*)&S->ef[i][jl * 8];
            const float4 eb = *(const float4*)&S->ef[i][jl * 8 + 4];
            const int    am = S->adjb[i][jl];
            const float4 sd4 = S->sdst[c * JC + jl];
            const float4 ss4 = S->ssrc[i];

            float vx = epb4.x + ss4.x + sd4.x;
            float vy = epb4.y + ss4.y + sd4.y;
            float vz = epb4.z + ss4.z + sd4.z;
            float vw = epb4.w + ss4.w + sd4.w;
            float4 we;
            we = S->epw[0]; vx += ea.x * we.x; vy += ea.x * we.y; vz += ea.x * we.z; vw += ea.x * we.w;
            we = S->epw[1]; vx += ea.y * we.x; vy += ea.y * we.y; vz += ea.y * we.z; vw += ea.y * we.w;
            we = S->epw[2]; vx += ea.z * we.x; vy += ea.z * we.y; vz += ea.z * we.z; vw += ea.z * we.w;
            we = S->epw[3]; vx += ea.w * we.x; vy += ea.w * we.y; vz += ea.w * we.z; vw += ea.w * we.w;
            we = S->epw[4]; vx += eb.x * we.x; vy += eb.x * we.y; vz += eb.x * we.z; vw += eb.x * we.w;
            we = S->epw[5]; vx += eb.y * we.x; vy += eb.y * we.y; vz += eb.y * we.z; vw += eb.y * we.w;
            we = S->epw[6]; vx += eb.z * we.x; vy += eb.z * we.y; vz += eb.z * we.z; vw += eb.z * we.w;
            we = S->epw[7]; vx += eb.w * we.x; vy += eb.w * we.y; vz += eb.w * we.z; vw += eb.w * we.w;

            vx = fmaxf(vx, 0.2f * vx);
            vy = fmaxf(vy, 0.2f * vy);
            vz = fmaxf(vz, 0.2f * vz);
            vw = fmaxf(vw, 0.2f * vw);

            const float w0 = am ? __expf(vx) : 0.f;
            const float w1 = am ? __expf(vy) : 0.f;
            const float w2 = am ? __expf(vz) : 0.f;
            const float w3 = am ? __expf(vw) : 0.f;

            // duplicated store at permuted row index i' = (i&7)*8 + (i>>3)
            const int ip = ((i & 7) << 3) + (i >> 3);
            const int wo = jl * WIPAD + ip;
            S->w2[0][wo] = make_float2(w0, w0);
            S->w2[1][wo] = make_float2(w1, w1);
            S->w2[2][wo] = make_float2(w2, w2);
            S->w2[3][wo] = make_float2(w3, w3);
            pden[p][0] += w0; pden[p][1] += w1; pden[p][2] += w2; pden[p][3] += w3;
        }

        CP_WAIT0();          // h(c) complete
        __syncthreads();     // syncB: w + h visible to all

        if (c + 1 < NCHUNK) {          // refill ef for next chunk (after syncB)
            prefetch_ef(S, i0, j0 + JC, ef, adj, t);
            CP_COMMIT();
        }

        // ---- phase 2: acc[i,d] += w[i,j] * h[j,h2,d]
        // w operand loaded pre-packed via LDS.64 (no pack MOVs); address
        // i' = r*8 + gi8, lanes' gi8 values 1 f2 apart -> conflict-free.
        const float* hbase = &S->hs[h2 * ODIM + d8 * 4];
        const u64* wplane = (const u64*)&S->w2[h2][0];
#pragma unroll 4
        for (int j = 0; j < JC; j++) {
            const ulonglong2* hb = (const ulonglong2*)(hbase + j * HD);
            const ulonglong2 p0 = hb[0];
            const ulonglong2 p1 = hb[8];   // +128B (odd-chunk half)
            const u64* wrow = wplane + j * WIPAD + gi8;
#pragma unroll
            for (int r = 0; r < 8; r++) {
                const u64 wp = wrow[r * 8];     // LDS.64, direct FFMA2 operand
                ffma2(acc2[r][0], wp, p0.x); ffma2(acc2[r][1], wp, p0.y);
                ffma2(acc2[r][2], wp, p1.x); ffma2(acc2[r][3], wp, p1.y);
            }
        }
        // no trailing barrier: h/w rewritten only after next syncA/syncB.
    }

    // ---- write additive partials (packed)
    float* pa = g_pacc[js];
#pragma unroll
    for (int r = 0; r < 8; r++) {
        ulonglong2* dst =
            (ulonglong2*)(pa + (size_t)(i0 + gi8 * 8 + r) * HD + h2 * ODIM + d8 * 8);
        ulonglong2 o0; o0.x = acc2[r][0]; o0.y = acc2[r][1];
        ulonglong2 o1; o1.x = acc2[r][2]; o1.y = acc2[r][3];
        dst[0] = o0;
        dst[1] = o1;
    }
    // denom: 16 j-lanes per i-row -> reduce within 16-lane groups
#pragma unroll
    for (int p = 0; p < 4; p++)
#pragma unroll
        for (int h = 0; h < 4; h++) {
            float v = pden[p][h];
#pragma unroll
            for (int o = 8; o; o >>= 1) v += __shfl_xor_sync(0xffffffffu, v, o);
            if (jl == 0)
                g_pden[js][(i0 + p * 16 + ih) * HEADS + h] = v;
        }
}

// ---------------- kernel 4: combine + normalize + layernorm ----------------
__global__ __launch_bounds__(256) void k_final(const float* __restrict__ gamma,
                                               const float* __restrict__ beta,
                                               float* __restrict__ out) {
    __shared__ float rs[4][2], rq[4][2];
    __shared__ float mean_s[4], rstd_s[4];

    const int t = threadIdx.x;
    const int r = t >> 6;
    const int s = t & 63;
    const int n = blockIdx.x * 4 + r;

    float4 v = make_float4(0.f, 0.f, 0.f, 0.f);
#pragma unroll
    for (int sp = 0; sp < JSPLIT; sp++) {
        const float4 p = *(const float4*)&g_pacc[sp][(size_t)n * HD + s * 4];
        v.x += p.x; v.y += p.y; v.z += p.z; v.w += p.w;
    }
    const int h = s >> 4;
    float den = 0.f;
#pragma unroll
    for (int sp = 0; sp < JSPLIT; sp++) den += g_pden[sp][n * HEADS + h];
    const float inv = __frcp_rn(den);
    v.x *= inv; v.y *= inv; v.z *= inv; v.w *= inv;

    float sum = v.x + v.y + v.z + v.w;
    float sq  = v.x * v.x + v.y * v.y + v.z * v.z + v.w * v.w;
#pragma unroll
    for (int o = 16; o; o >>= 1) {
        sum += __shfl_xor_sync(0xffffffffu, sum, o);
        sq  += __shfl_xor_sync(0xffffffffu, sq, o);
    }
    const int half = (t >> 5) & 1;
    if ((t & 31) == 0) { rs[r][half] = sum; rq[r][half] = sq; }
    __syncthreads();
    if (s == 0) {
        const float S = rs[r][0] + rs[r][1];
        const float Q = rq[r][0] + rq[r][1];
        const float m = S * (1.f / HD);
        const float var = Q * (1.f / HD) - m * m;
        mean_s[r] = m;
        rstd_s[r] = rsqrtf(var + 1e-5f);
    }
    __syncthreads();
    const float m   = mean_s[r];
    const float rsd = rstd_s[r];
    const float4 g = ((const float4*)gamma)[s];
    const float4 b = ((const float4*)beta)[s];
    float4 o;
    o.x = (v.x - m) * rsd * g.x + b.x;
    o.y = (v.y - m) * rsd * g.y + b.y;
    o.z = (v.z - m) * rsd * g.z + b.z;
    o.w = (v.w - m) * rsd * g.w + b.w;
    ((float4*)out)[(size_t)n * (HD / 4) + s] = o;
}

// ---------------- launch ----------------------------------------------------
extern "C" void kernel_launch(void* const* d_in, const int* in_sizes, int n_in,
                              void* d_out, int out_size) {
    const float* x      = (const float*)d_in[0];
    const int*   adj    = (const int*)  d_in[1];
    const float* ef     = (const float*)d_in[2];
    const float* W      = (const float*)d_in[3];
    const float* a_src  = (const float*)d_in[4];
    const float* a_dst  = (const float*)d_in[5];
    const float* ep_w   = (const float*)d_in[6];
    const float* ep_b   = (const float*)d_in[7];
    const float* gamma  = (const float*)d_in[8];
    const float* beta   = (const float*)d_in[9];
    float* out = (float*)d_out;

    const int smem_bytes = (int)sizeof(SmemAttn);   // ~94.5 KB
    cudaFuncSetAttribute(k_attn, cudaFuncAttributeMaxDynamicSharedMemorySize,
                         smem_bytes);

    k_proj  <<<NN / 16, 256>>>(x, W);
    k_scores<<<(NN * HEADS) / 256, 256>>>(a_src, a_dst);
    k_attn  <<<dim3(NN / TI, JSPLIT), 256, smem_bytes>>>(ef, adj, ep_w, ep_b);
    k_final <<<NN / 4, 256>>>(gamma, beta, out);
}

// round 16
// speedup vs baseline: 2.0866x; 1.8326x over previous
#include <cuda_runtime.h>
#include <cuda_bf16.h>
#include <cstddef>
#include <cstdint>

#define NN     3072
#define IND    128
#define HEADS  4
#define ODIM   64
#define EDIM   8
#define HD     256        // HEADS*ODIM
#define TI     64         // i-rows per block
#define JC     16         // j per chunk
#define WROW   20         // w row stride (floats): 20*gid+tid4 covers 32 banks
#define HSROW  264        // hs row stride (floats): 8*tid4+gid covers 32 banks
#define JSPLIT 6
#define JRANGE (NN / JSPLIT)   // 512
#define NCHUNK (JRANGE / JC)   // 32

typedef unsigned long long u64;

// ---------------- scratch (static device globals: no runtime allocs) -------
__device__ __align__(256) float  g_h[NN * HD];                 // 3 MB (tf32-rounded)
__device__ __align__(256) float4 g_ssrc[NN];
__device__ __align__(256) float4 g_sdst[NN];
__device__ __align__(256) float  g_pacc[JSPLIT][NN * HD];      // 18.9 MB
__device__ __align__(256) float  g_pden[JSPLIT][NN * HEADS];

// ---------------- tf32 / mma / cp.async helpers ----------------------------
__device__ __forceinline__ float tf32r(float x) {
    uint32_t u; asm("cvt.rna.tf32.f32 %0, %1;" : "=r"(u) : "f"(x));
    return __uint_as_float(u);
}
__device__ __forceinline__ void mma8(float* c, const uint32_t* a,
                                     uint32_t b0, uint32_t b1) {
    asm volatile(
        "mma.sync.aligned.m16n8k8.row.col.f32.tf32.tf32.f32 "
        "{%0,%1,%2,%3}, {%4,%5,%6,%7}, {%8,%9}, {%0,%1,%2,%3};"
        : "+f"(c[0]), "+f"(c[1]), "+f"(c[2]), "+f"(c[3])
        : "r"(a[0]), "r"(a[1]), "r"(a[2]), "r"(a[3]), "r"(b0), "r"(b1));
}
__device__ __forceinline__ void cpa16(uint32_t s, const void* g) {
    asm volatile("cp.async.cg.shared.global [%0], [%1], 16;" :: "r"(s), "l"(g));
}
#define CP_COMMIT() asm volatile("cp.async.commit_group;")
#define CP_WAIT0()  asm volatile("cp.async.wait_group 0;" ::: "memory")

// ---------------- dynamic smem layout for k_attn ---------------------------
struct __align__(16) SmemAttn {
    float  ef[TI][JC * EDIM];      // 32 KB : edge_feats tile (single buffer)
    float  hs[JC * HSROW];         // 16.9 KB : h tile, plain rows stride 264
    int    adjb[TI][JC];           // 4 KB  : adjacency tile
    float  w[HEADS][TI * WROW + 8];// 20.6 KB : tf32-rounded attention weights
    float4 sdst[JRANGE];           // 8 KB
    float4 ssrc[TI];               // 1 KB
    float4 epw[EDIM];
    float4 epb;
};                                 // ~83.7 KB -> 2 blocks/SM

// ---------------- kernel 1: h = x @ W, output tf32-rounded ----------------
__global__ __launch_bounds__(256) void k_proj(const float* __restrict__ x,
                                              const float* __restrict__ W) {
    __shared__ float4 xs4[16 * IND / 4];
    const int t  = threadIdx.x;
    const int i0 = blockIdx.x * 16;

    const float4* xg4 = (const float4*)(x + (size_t)i0 * IND);
#pragma unroll
    for (int k = 0; k < 2; k++) xs4[t + 256 * k] = xg4[t + 256 * k];
    __syncthreads();

    float acc[16];
#pragma unroll
    for (int r = 0; r < 16; r++) acc[r] = 0.f;

    for (int k4 = 0; k4 < IND / 4; k4++) {
        const float w0 = W[(k4 * 4 + 0) * HD + t];
        const float w1 = W[(k4 * 4 + 1) * HD + t];
        const float w2 = W[(k4 * 4 + 2) * HD + t];
        const float w3 = W[(k4 * 4 + 3) * HD + t];
#pragma unroll
        for (int r = 0; r < 16; r++) {
            const float4 xv = xs4[r * (IND / 4) + k4];
            acc[r] += xv.x * w0 + xv.y * w1 + xv.z * w2 + xv.w * w3;
        }
    }
    // tf32-round h once here so phase-2 MMA needs no cvt at all
#pragma unroll
    for (int r = 0; r < 16; r++)
        g_h[(size_t)(i0 + r) * HD + t] = tf32r(acc[r]);
}

// ---------------- kernel 2: s_src / s_dst ---------------------------------
__global__ __launch_bounds__(256) void k_scores(const float* __restrict__ a_src,
                                                const float* __restrict__ a_dst) {
    const int tid = blockIdx.x * blockDim.x + threadIdx.x;
    const int n = tid >> 2, h = tid & 3;
    const float4* hv = (const float4*)(g_h + (size_t)n * HD + h * ODIM);
    const float4* as = (const float4*)(a_src + h * ODIM);
    const float4* ad = (const float4*)(a_dst + h * ODIM);
    float ss = 0.f, sd = 0.f;
#pragma unroll
    for (int q = 0; q < ODIM / 4; q++) {
        const float4 hq = hv[q], aq = as[q], dq = ad[q];
        ss += hq.x * aq.x + hq.y * aq.y + hq.z * aq.z + hq.w * aq.w;
        sd += hq.x * dq.x + hq.y * dq.y + hq.z * dq.z + hq.w * dq.w;
    }
    ((float*)g_ssrc)[tid] = ss;
    ((float*)g_sdst)[tid] = sd;
}

// ---------------- prefetch helpers (cp.async) ------------------------------
__device__ __forceinline__ void prefetch_ef(SmemAttn* S, int i0, int j0,
                                            const float* __restrict__ ef,
                                            const int*   __restrict__ adj, int t) {
    // ef tile: 64 rows x 512B = 2048 x 16B
#pragma unroll
    for (int k = 0; k < 8; k++) {
        const int u  = t + k * 256;
        const int i  = u >> 5;             // 32 units per row
        const int uo = u & 31;
        const uint32_t dst = (uint32_t)__cvta_generic_to_shared(&S->ef[i][uo * 4]);
        cpa16(dst, ef + ((size_t)(i0 + i) * NN + j0) * EDIM + uo * 4);
    }
    // adj tile: 64 x 16 ints = 256 x 16B
    {
        const int i  = t >> 2;
        const int j4 = t & 3;
        const uint32_t dst = (uint32_t)__cvta_generic_to_shared(&S->adjb[i][j4 * 4]);
        cpa16(dst, adj + (size_t)(i0 + i) * NN + j0 + j4 * 4);
    }
}

// h tile: 16 rows x 256 floats, plain layout with row stride HSROW=264.
__device__ __forceinline__ void prefetch_h(SmemAttn* S, int j0, int t) {
#pragma unroll
    for (int k = 0; k < 4; k++) {
        const int u   = t + k * 256;
        const int row = u >> 6;            // 64 x 16B units per j-row
        const int cu  = u & 63;
        const uint32_t dst = (uint32_t)__cvta_generic_to_shared(
            &S->hs[row * HSROW + cu * 4]);
        cpa16(dst, g_h + (size_t)(j0 + row) * HD + cu * 4);
    }
}

// ---------------- kernel 3: fused attention, tf32 tensor-core phase-2 ------
__global__ __launch_bounds__(256, 2) void k_attn(const float* __restrict__ ef,
                                                 const int*   __restrict__ adj,
                                                 const float* __restrict__ ep_w,
                                                 const float* __restrict__ ep_b) {
    extern __shared__ char smem_raw[];
    SmemAttn* S = (SmemAttn*)smem_raw;

    const int t     = threadIdx.x;
    const int i0    = blockIdx.x * TI;
    const int js    = blockIdx.y;
    const int jbase = js * JRANGE;

    if (t < EDIM) S->epw[t] = ((const float4*)ep_w)[t];
    if (t == EDIM) S->epb = *(const float4*)ep_b;
    if (t < TI) S->ssrc[t] = g_ssrc[i0 + t];
    for (int k = t; k < JRANGE; k += 256) S->sdst[k] = g_sdst[jbase + k];

    prefetch_ef(S, i0, jbase, ef, adj, t);
    CP_COMMIT();

    // phase-1 identity: 16 j-lanes x 16 i-groups, 4 passes (R8-identical)
    const int jl  = t & 15;
    const int ih  = t >> 4;
    // phase-2 identity: warp = (head, i-half); m16n8k8 fragment coords
    const int wid   = t >> 5;
    const int lane  = t & 31;
    const int h2m   = wid >> 1;        // head
    const int mhalf = wid & 1;         // i-half: rows [mhalf*32, mhalf*32+32)
    const int gid   = lane >> 2;       // 0..7
    const int tid4  = lane & 3;        // 0..3

    float cfrag[2][8][4];              // 64 fp32 accumulators (2 m16 x 8 n8)
#pragma unroll
    for (int mi = 0; mi < 2; mi++)
#pragma unroll
        for (int n8 = 0; n8 < 8; n8++)
#pragma unroll
            for (int q = 0; q < 4; q++) cfrag[mi][n8][q] = 0.f;

    float pden[4][4];
#pragma unroll
    for (int p = 0; p < 4; p++)
#pragma unroll
        for (int h = 0; h < 4; h++) pden[p][h] = 0.f;

    for (int c = 0; c < NCHUNK; c++) {
        const int j0 = jbase + c * JC;

        CP_WAIT0();          // ef(c) [and stray h(c-1)] complete
        __syncthreads();     // syncA: ef visible; phase-2(c-1) readers done

        prefetch_h(S, j0, t);   // h buffer free after syncA
        CP_COMMIT();

        // ---- phase 1: w = adj ? exp(leaky(ssrc+sdst+edge@epw+epb)) : 0
        //      (stored tf32-rounded; pden uses the SAME rounded values)
        const float4 epb4 = S->epb;
#pragma unroll
        for (int p = 0; p < 4; p++) {
            const int i  = p * 16 + ih;
            const float4 ea = *(const float4*)&S->ef[i][jl * 8];
            const float4 eb = *(const float4*)&S->ef[i][jl * 8 + 4];
            const int    am = S->adjb[i][jl];
            const float4 sd4 = S->sdst[c * JC + jl];
            const float4 ss4 = S->ssrc[i];

            float vx = epb4.x + ss4.x + sd4.x;
            float vy = epb4.y + ss4.y + sd4.y;
            float vz = epb4.z + ss4.z + sd4.z;
            float vw = epb4.w + ss4.w + sd4.w;
            float4 we;
            we = S->epw[0]; vx += ea.x * we.x; vy += ea.x * we.y; vz += ea.x * we.z; vw += ea.x * we.w;
            we = S->epw[1]; vx += ea.y * we.x; vy += ea.y * we.y; vz += ea.y * we.z; vw += ea.y * we.w;
            we = S->epw[2]; vx += ea.z * we.x; vy += ea.z * we.y; vz += ea.z * we.z; vw += ea.z * we.w;
            we = S->epw[3]; vx += ea.w * we.x; vy += ea.w * we.y; vz += ea.w * we.z; vw += ea.w * we.w;
            we = S->epw[4]; vx += eb.x * we.x; vy += eb.x * we.y; vz += eb.x * we.z; vw += eb.x * we.w;
            we = S->epw[5]; vx += eb.y * we.x; vy += eb.y * we.y; vz += eb.y * we.z; vw += eb.y * we.w;
            we = S->epw[6]; vx += eb.z * we.x; vy += eb.z * we.y; vz += eb.z * we.z; vw += eb.z * we.w;
            we = S->epw[7]; vx += eb.w * we.x; vy += eb.w * we.y; vz += eb.w * we.z; vw += eb.w * we.w;

            vx = fmaxf(vx, 0.2f * vx);
            vy = fmaxf(vy, 0.2f * vy);
            vz = fmaxf(vz, 0.2f * vz);
            vw = fmaxf(vw, 0.2f * vw);

            const float w0 = am ? tf32r(__expf(vx)) : 0.f;
            const float w1 = am ? tf32r(__expf(vy)) : 0.f;
            const float w2 = am ? tf32r(__expf(vz)) : 0.f;
            const float w3 = am ? tf32r(__expf(vw)) : 0.f;

            S->w[0][i * WROW + jl] = w0;
            S->w[1][i * WROW + jl] = w1;
            S->w[2][i * WROW + jl] = w2;
            S->w[3][i * WROW + jl] = w3;
            pden[p][0] += w0; pden[p][1] += w1; pden[p][2] += w2; pden[p][3] += w3;
        }

        CP_WAIT0();          // h(c) complete
        __syncthreads();     // syncB: w + h visible to all

        if (c + 1 < NCHUNK) {          // refill ef for next chunk
            prefetch_ef(S, i0, j0 + JC, ef, adj, t);
            CP_COMMIT();
        }

        // ---- phase 2: C += W(64x16) * H(16x64) per head, via m16n8k8 tf32
        const float* wp = &S->w[h2m][0];
        const float* hp = &S->hs[0];
#pragma unroll
        for (int k8 = 0; k8 < 2; k8++) {
            const int jb = k8 * 8;
            uint32_t a[2][4];
#pragma unroll
            for (int mi = 0; mi < 2; mi++) {
                const float* ar = wp + (mhalf * 32 + mi * 16 + gid) * WROW + jb;
                a[mi][0] = __float_as_uint(ar[tid4]);
                a[mi][1] = __float_as_uint(ar[8 * WROW + tid4]);
                a[mi][2] = __float_as_uint(ar[tid4 + 4]);
                a[mi][3] = __float_as_uint(ar[8 * WROW + tid4 + 4]);
            }
#pragma unroll
            for (int n8 = 0; n8 < 8; n8++) {
                const float* br = hp + (jb + tid4) * HSROW + h2m * ODIM + n8 * 8 + gid;
                const uint32_t b0 = __float_as_uint(br[0]);
                const uint32_t b1 = __float_as_uint(br[4 * HSROW]);
                mma8(cfrag[0][n8], a[0], b0, b1);
                mma8(cfrag[1][n8], a[1], b0, b1);
            }
        }
        // no trailing barrier: w/h rewritten only after next syncA/syncB.
    }

    // ---- write additive partials from C fragments
    float* pa = g_pacc[js];
#pragma unroll
    for (int mi = 0; mi < 2; mi++) {
        const int r0 = i0 + mhalf * 32 + mi * 16 + gid;
#pragma unroll
        for (int n8 = 0; n8 < 8; n8++) {
            const int col = h2m * ODIM + n8 * 8 + 2 * tid4;
            *(float2*)&pa[(size_t)r0 * HD + col] =
                make_float2(cfrag[mi][n8][0], cfrag[mi][n8][1]);
            *(float2*)&pa[(size_t)(r0 + 8) * HD + col] =
                make_float2(cfrag[mi][n8][2], cfrag[mi][n8][3]);
        }
    }
    // denom: 16 j-lanes per i-row -> reduce within 16-lane groups
#pragma unroll
    for (int p = 0; p < 4; p++)
#pragma unroll
        for (int h = 0; h < 4; h++) {
            float v = pden[p][h];
#pragma unroll
            for (int o = 8; o; o >>= 1) v += __shfl_xor_sync(0xffffffffu, v, o);
            if (jl == 0)
                g_pden[js][(i0 + p * 16 + ih) * HEADS + h] = v;
        }
}

// ---------------- kernel 4: combine + normalize + layernorm ----------------
__global__ __launch_bounds__(256) void k_final(const float* __restrict__ gamma,
                                               const float* __restrict__ beta,
                                               float* __restrict__ out) {
    __shared__ float rs[4][2], rq[4][2];
    __shared__ float mean_s[4], rstd_s[4];

    const int t = threadIdx.x;
    const int r = t >> 6;
    const int s = t & 63;
    const int n = blockIdx.x * 4 + r;

    float4 v = make_float4(0.f, 0.f, 0.f, 0.f);
#pragma unroll
    for (int sp = 0; sp < JSPLIT; sp++) {
        const float4 p = *(const float4*)&g_pacc[sp][(size_t)n * HD + s * 4];
        v.x += p.x; v.y += p.y; v.z += p.z; v.w += p.w;
    }
    const int h = s >> 4;
    float den = 0.f;
#pragma unroll
    for (int sp = 0; sp < JSPLIT; sp++) den += g_pden[sp][n * HEADS + h];
    const float inv = __frcp_rn(den);
    v.x *= inv; v.y *= inv; v.z *= inv; v.w *= inv;

    float sum = v.x + v.y + v.z + v.w;
    float sq  = v.x * v.x + v.y * v.y + v.z * v.z + v.w * v.w;
#pragma unroll
    for (int o = 16; o; o >>= 1) {
        sum += __shfl_xor_sync(0xffffffffu, sum, o);
        sq  += __shfl_xor_sync(0xffffffffu, sq, o);
    }
    const int half = (t >> 5) & 1;
    if ((t & 31) == 0) { rs[r][half] = sum; rq[r][half] = sq; }
    __syncthreads();
    if (s == 0) {
        const float S = rs[r][0] + rs[r][1];
        const float Q = rq[r][0] + rq[r][1];
        const float m = S * (1.f / HD);
        const float var = Q * (1.f / HD) - m * m;
        mean_s[r] = m;
        rstd_s[r] = rsqrtf(var + 1e-5f);
    }
    __syncthreads();
    const float m   = mean_s[r];
    const float rsd = rstd_s[r];
    const float4 g = ((const float4*)gamma)[s];
    const float4 b = ((const float4*)beta)[s];
    float4 o;
    o.x = (v.x - m) * rsd * g.x + b.x;
    o.y = (v.y - m) * rsd * g.y + b.y;
    o.z = (v.z - m) * rsd * g.z + b.z;
    o.w = (v.w - m) * rsd * g.w + b.w;
    ((float4*)out)[(size_t)n * (HD / 4) + s] = o;
}

// ---------------- launch ----------------------------------------------------
extern "C" void kernel_launch(void* const* d_in, const int* in_sizes, int n_in,
                              void* d_out, int out_size) {
    const float* x      = (const float*)d_in[0];
    const int*   adj    = (const int*)  d_in[1];
    const float* ef     = (const float*)d_in[2];
    const float* W      = (const float*)d_in[3];
    const float* a_src  = (const float*)d_in[4];
    const float* a_dst  = (const float*)d_in[5];
    const float* ep_w   = (const float*)d_in[6];
    const float* ep_b   = (const float*)d_in[7];
    const float* gamma  = (const float*)d_in[8];
    const float* beta   = (const float*)d_in[9];
    float* out = (float*)d_out;

    const int smem_bytes = (int)sizeof(SmemAttn);   // ~83.7 KB
    cudaFuncSetAttribute(k_attn, cudaFuncAttributeMaxDynamicSharedMemorySize,
                         smem_bytes);

    k_proj  <<<NN / 16, 256>>>(x, W);
    k_scores<<<(NN * HEADS) / 256, 256>>>(a_src, a_dst);
    k_attn  <<<dim3(NN / TI, JSPLIT), 256, smem_bytes>>>(ef, adj, ep_w, ep_b);
    k_final <<<NN / 4, 256>>>(gamma, beta, out);
}

// round 17
// speedup vs baseline: 2.0997x; 1.0063x over previous
#include <cuda_runtime.h>
#include <cuda_bf16.h>
#include <cstddef>
#include <cstdint>

#define NN     3072
#define IND    128
#define HEADS  4
#define ODIM   64
#define EDIM   8
#define HD     256        // HEADS*ODIM
#define TI     64         // i-rows per block
#define JC     16         // j per chunk
#define WROW   20         // w row stride (floats): 20*gid+tid4 covers 32 banks
#define HSROW  264        // hs row stride (floats): 8*tid4+gid covers 32 banks
#define JSPLIT 6
#define JRANGE (NN / JSPLIT)   // 512
#define NCHUNK (JRANGE / JC)   // 32

typedef unsigned long long u64;

// ---------------- scratch (static device globals: no runtime allocs) -------
__device__ __align__(256) float  g_h[NN * HD];                 // 3 MB (tf32-rounded)
__device__ __align__(256) float4 g_ssrc[NN];
__device__ __align__(256) float4 g_sdst[NN];
__device__ __align__(256) float  g_pacc[JSPLIT][NN * HD];      // 18.9 MB
__device__ __align__(256) float  g_pden[JSPLIT][NN * HEADS];

// ---------------- tf32 / mma / cp.async helpers ----------------------------
__device__ __forceinline__ float tf32r(float x) {
    uint32_t u; asm("cvt.rna.tf32.f32 %0, %1;" : "=r"(u) : "f"(x));
    return __uint_as_float(u);
}
__device__ __forceinline__ void mma8(float* c, const uint32_t* a,
                                     uint32_t b0, uint32_t b1) {
    asm volatile(
        "mma.sync.aligned.m16n8k8.row.col.f32.tf32.tf32.f32 "
        "{%0,%1,%2,%3}, {%4,%5,%6,%7}, {%8,%9}, {%0,%1,%2,%3};"
        : "+f"(c[0]), "+f"(c[1]), "+f"(c[2]), "+f"(c[3])
        : "r"(a[0]), "r"(a[1]), "r"(a[2]), "r"(a[3]), "r"(b0), "r"(b1));
}
__device__ __forceinline__ void cpa16(uint32_t s, const void* g) {
    asm volatile("cp.async.cg.shared.global [%0], [%1], 16;" :: "r"(s), "l"(g));
}
#define CP_COMMIT() asm volatile("cp.async.commit_group;")
#define CP_WAIT0()  asm volatile("cp.async.wait_group 0;" ::: "memory")

// ---------------- dynamic smem layout for k_attn ---------------------------
struct __align__(16) SmemAttn {
    float  ef[TI][JC * EDIM];      // 32 KB : edge_feats tile (single buffer)
    float  hs[JC * HSROW];         // 16.9 KB : h tile, plain rows stride 264
    int    adjb[TI][JC];           // 4 KB  : adjacency tile
    float  w[HEADS][TI * WROW + 8];// 20.6 KB : tf32-rounded attention weights
    float4 sdst[JRANGE];           // 8 KB
    float4 ssrc[TI];               // 1 KB
    float4 epw[EDIM];
    float4 epb;
};                                 // ~83.7 KB -> 2 blocks/SM

// ---------------- kernel 1: h = x @ W, output tf32-rounded ----------------
__global__ __launch_bounds__(256) void k_proj(const float* __restrict__ x,
                                              const float* __restrict__ W) {
    __shared__ float4 xs4[16 * IND / 4];
    const int t  = threadIdx.x;
    const int i0 = blockIdx.x * 16;

    const float4* xg4 = (const float4*)(x + (size_t)i0 * IND);
#pragma unroll
    for (int k = 0; k < 2; k++) xs4[t + 256 * k] = xg4[t + 256 * k];
    __syncthreads();

    float acc[16];
#pragma unroll
    for (int r = 0; r < 16; r++) acc[r] = 0.f;

    for (int k4 = 0; k4 < IND / 4; k4++) {
        const float w0 = W[(k4 * 4 + 0) * HD + t];
        const float w1 = W[(k4 * 4 + 1) * HD + t];
        const float w2 = W[(k4 * 4 + 2) * HD + t];
        const float w3 = W[(k4 * 4 + 3) * HD + t];
#pragma unroll
        for (int r = 0; r < 16; r++) {
            const float4 xv = xs4[r * (IND / 4) + k4];
            acc[r] += xv.x * w0 + xv.y * w1 + xv.z * w2 + xv.w * w3;
        }
    }
    // tf32-round h once here so phase-2 MMA needs no cvt at all
#pragma unroll
    for (int r = 0; r < 16; r++)
        g_h[(size_t)(i0 + r) * HD + t] = tf32r(acc[r]);
}

// ---------------- kernel 2: s_src / s_dst ---------------------------------
__global__ __launch_bounds__(256) void k_scores(const float* __restrict__ a_src,
                                                const float* __restrict__ a_dst) {
    const int tid = blockIdx.x * blockDim.x + threadIdx.x;
    const int n = tid >> 2, h = tid & 3;
    const float4* hv = (const float4*)(g_h + (size_t)n * HD + h * ODIM);
    const float4* as = (const float4*)(a_src + h * ODIM);
    const float4* ad = (const float4*)(a_dst + h * ODIM);
    float ss = 0.f, sd = 0.f;
#pragma unroll
    for (int q = 0; q < ODIM / 4; q++) {
        const float4 hq = hv[q], aq = as[q], dq = ad[q];
        ss += hq.x * aq.x + hq.y * aq.y + hq.z * aq.z + hq.w * aq.w;
        sd += hq.x * dq.x + hq.y * dq.y + hq.z * dq.z + hq.w * dq.w;
    }
    ((float*)g_ssrc)[tid] = ss;
    ((float*)g_sdst)[tid] = sd;
}

// ---------------- prefetch helpers (cp.async) ------------------------------
__device__ __forceinline__ void prefetch_ef(SmemAttn* S, int i0, int j0,
                                            const float* __restrict__ ef,
                                            const int*   __restrict__ adj, int t) {
    // ef tile: 64 rows x 512B = 2048 x 16B
#pragma unroll
    for (int k = 0; k < 8; k++) {
        const int u  = t + k * 256;
        const int i  = u >> 5;             // 32 units per row
        const int uo = u & 31;
        const uint32_t dst = (uint32_t)__cvta_generic_to_shared(&S->ef[i][uo * 4]);
        cpa16(dst, ef + ((size_t)(i0 + i) * NN + j0) * EDIM + uo * 4);
    }
    // adj tile: 64 x 16 ints = 256 x 16B
    {
        const int i  = t >> 2;
        const int j4 = t & 3;
        const uint32_t dst = (uint32_t)__cvta_generic_to_shared(&S->adjb[i][j4 * 4]);
        cpa16(dst, adj + (size_t)(i0 + i) * NN + j0 + j4 * 4);
    }
}

// h tile: 16 rows x 256 floats, plain layout with row stride HSROW=264.
__device__ __forceinline__ void prefetch_h(SmemAttn* S, int j0, int t) {
#pragma unroll
    for (int k = 0; k < 4; k++) {
        const int u   = t + k * 256;
        const int row = u >> 6;            // 64 x 16B units per j-row
        const int cu  = u & 63;
        const uint32_t dst = (uint32_t)__cvta_generic_to_shared(
            &S->hs[row * HSROW + cu * 4]);
        cpa16(dst, g_h + (size_t)(j0 + row) * HD + cu * 4);
    }
}

// ---------------- kernel 3: fused attention, tf32 tensor-core phase-2 ------
__global__ __launch_bounds__(256, 2) void k_attn(const float* __restrict__ ef,
                                                 const int*   __restrict__ adj,
                                                 const float* __restrict__ ep_w,
                                                 const float* __restrict__ ep_b) {
    extern __shared__ char smem_raw[];
    SmemAttn* S = (SmemAttn*)smem_raw;

    const int t     = threadIdx.x;
    const int i0    = blockIdx.x * TI;
    const int js    = blockIdx.y;
    const int jbase = js * JRANGE;

    if (t < EDIM) S->epw[t] = ((const float4*)ep_w)[t];
    if (t == EDIM) S->epb = *(const float4*)ep_b;
    if (t < TI) S->ssrc[t] = g_ssrc[i0 + t];
    for (int k = t; k < JRANGE; k += 256) S->sdst[k] = g_sdst[jbase + k];

    prefetch_ef(S, i0, jbase, ef, adj, t);
    CP_COMMIT();

    // phase-1 identity: 16 j-lanes x 16 i-groups, 4 passes (R8-identical)
    const int jl  = t & 15;
    const int ih  = t >> 4;
    // phase-2 identity: warp = (head, i-half); m16n8k8 fragment coords
    const int wid   = t >> 5;
    const int lane  = t & 31;
    const int h2m   = wid >> 1;        // head
    const int mhalf = wid & 1;         // i-half: rows [mhalf*32, mhalf*32+32)
    const int gid   = lane >> 2;       // 0..7
    const int tid4  = lane & 3;        // 0..3

    float cfrag[2][8][4];              // 64 fp32 accumulators (2 m16 x 8 n8)
#pragma unroll
    for (int mi = 0; mi < 2; mi++)
#pragma unroll
        for (int n8 = 0; n8 < 8; n8++)
#pragma unroll
            for (int q = 0; q < 4; q++) cfrag[mi][n8][q] = 0.f;

    float pden[4][4];
#pragma unroll
    for (int p = 0; p < 4; p++)
#pragma unroll
        for (int h = 0; h < 4; h++) pden[p][h] = 0.f;

    for (int c = 0; c < NCHUNK; c++) {
        const int j0 = jbase + c * JC;

        CP_WAIT0();          // ef(c) [and stray h(c-1)] complete
        __syncthreads();     // syncA: ef visible; phase-2(c-1) readers done

        prefetch_h(S, j0, t);   // h buffer free after syncA
        CP_COMMIT();

        // ---- phase 1: w = adj ? exp(leaky(ssrc+sdst+edge@epw+epb)) : 0
        //      (stored tf32-rounded; pden uses the SAME rounded values)
        const float4 epb4 = S->epb;
#pragma unroll
        for (int p = 0; p < 4; p++) {
            const int i  = p * 16 + ih;
            const float4 ea = *(const float4*)&S->ef[i][jl * 8];
            const float4 eb = *(const float4*)&S->ef[i][jl * 8 + 4];
            const int    am = S->adjb[i][jl];
            const float4 sd4 = S->sdst[c * JC + jl];
            const float4 ss4 = S->ssrc[i];

            float vx = epb4.x + ss4.x + sd4.x;
            float vy = epb4.y + ss4.y + sd4.y;
            float vz = epb4.z + ss4.z + sd4.z;
            float vw = epb4.w + ss4.w + sd4.w;
            float4 we;
            we = S->epw[0]; vx += ea.x * we.x; vy += ea.x * we.y; vz += ea.x * we.z; vw += ea.x * we.w;
            we = S->epw[1]; vx += ea.y * we.x; vy += ea.y * we.y; vz += ea.y * we.z; vw += ea.y * we.w;
            we = S->epw[2]; vx += ea.z * we.x; vy += ea.z * we.y; vz += ea.z * we.z; vw += ea.z * we.w;
            we = S->epw[3]; vx += ea.w * we.x; vy += ea.w * we.y; vz += ea.w * we.z; vw += ea.w * we.w;
            we = S->epw[4]; vx += eb.x * we.x; vy += eb.x * we.y; vz += eb.x * we.z; vw += eb.x * we.w;
            we = S->epw[5]; vx += eb.y * we.x; vy += eb.y * we.y; vz += eb.y * we.z; vw += eb.y * we.w;
            we = S->epw[6]; vx += eb.z * we.x; vy += eb.z * we.y; vz += eb.z * we.z; vw += eb.z * we.w;
            we = S->epw[7]; vx += eb.w * we.x; vy += eb.w * we.y; vz += eb.w * we.z; vw += eb.w * we.w;

            vx = fmaxf(vx, 0.2f * vx);
            vy = fmaxf(vy, 0.2f * vy);
            vz = fmaxf(vz, 0.2f * vz);
            vw = fmaxf(vw, 0.2f * vw);

            const float w0 = am ? tf32r(__expf(vx)) : 0.f;
            const float w1 = am ? tf32r(__expf(vy)) : 0.f;
            const float w2 = am ? tf32r(__expf(vz)) : 0.f;
            const float w3 = am ? tf32r(__expf(vw)) : 0.f;

            S->w[0][i * WROW + jl] = w0;
            S->w[1][i * WROW + jl] = w1;
            S->w[2][i * WROW + jl] = w2;
            S->w[3][i * WROW + jl] = w3;
            pden[p][0] += w0; pden[p][1] += w1; pden[p][2] += w2; pden[p][3] += w3;
        }

        CP_WAIT0();          // h(c) complete
        __syncthreads();     // syncB: w + h visible to all

        if (c + 1 < NCHUNK) {          // refill ef for next chunk
            prefetch_ef(S, i0, j0 + JC, ef, adj, t);
            CP_COMMIT();
        }

        // ---- phase 2: C += W(64x16) * H(16x64) per head, via m16n8k8 tf32
        const float* wp = &S->w[h2m][0];
        const float* hp = &S->hs[0];
#pragma unroll
        for (int k8 = 0; k8 < 2; k8++) {
            const int jb = k8 * 8;
            uint32_t a[2][4];
#pragma unroll
            for (int mi = 0; mi < 2; mi++) {
                const float* ar = wp + (mhalf * 32 + mi * 16 + gid) * WROW + jb;
                a[mi][0] = __float_as_uint(ar[tid4]);
                a[mi][1] = __float_as_uint(ar[8 * WROW + tid4]);
                a[mi][2] = __float_as_uint(ar[tid4 + 4]);
                a[mi][3] = __float_as_uint(ar[8 * WROW + tid4 + 4]);
            }
#pragma unroll
            for (int n8 = 0; n8 < 8; n8++) {
                const float* br = hp + (jb + tid4) * HSROW + h2m * ODIM + n8 * 8 + gid;
                const uint32_t b0 = __float_as_uint(br[0]);
                const uint32_t b1 = __float_as_uint(br[4 * HSROW]);
                mma8(cfrag[0][n8], a[0], b0, b1);
                mma8(cfrag[1][n8], a[1], b0, b1);
            }
        }
        // no trailing barrier: w/h rewritten only after next syncA/syncB.
    }

    // ---- write additive partials from C fragments
    float* pa = g_pacc[js];
#pragma unroll
    for (int mi = 0; mi < 2; mi++) {
        const int r0 = i0 + mhalf * 32 + mi * 16 + gid;
#pragma unroll
        for (int n8 = 0; n8 < 8; n8++) {
            const int col = h2m * ODIM + n8 * 8 + 2 * tid4;
            *(float2*)&pa[(size_t)r0 * HD + col] =
                make_float2(cfrag[mi][n8][0], cfrag[mi][n8][1]);
            *(float2*)&pa[(size_t)(r0 + 8) * HD + col] =
                make_float2(cfrag[mi][n8][2], cfrag[mi][n8][3]);
        }
    }
    // denom: 16 j-lanes per i-row -> reduce within 16-lane groups
#pragma unroll
    for (int p = 0; p < 4; p++)
#pragma unroll
        for (int h = 0; h < 4; h++) {
            float v = pden[p][h];
#pragma unroll
            for (int o = 8; o; o >>= 1) v += __shfl_xor_sync(0xffffffffu, v, o);
            if (jl == 0)
                g_pden[js][(i0 + p * 16 + ih) * HEADS + h] = v;
        }
}

// ---------------- kernel 4: combine + normalize + layernorm ----------------
__global__ __launch_bounds__(256) void k_final(const float* __restrict__ gamma,
                                               const float* __restrict__ beta,
                                               float* __restrict__ out) {
    __shared__ float rs[4][2], rq[4][2];
    __shared__ float mean_s[4], rstd_s[4];

    const int t = threadIdx.x;
    const int r = t >> 6;
    const int s = t & 63;
    const int n = blockIdx.x * 4 + r;

    float4 v = make_float4(0.f, 0.f, 0.f, 0.f);
#pragma unroll
    for (int sp = 0; sp < JSPLIT; sp++) {
        const float4 p = *(const float4*)&g_pacc[sp][(size_t)n * HD + s * 4];
        v.x += p.x; v.y += p.y; v.z += p.z; v.w += p.w;
    }
    const int h = s >> 4;
    float den = 0.f;
#pragma unroll
    for (int sp = 0; sp < JSPLIT; sp++) den += g_pden[sp][n * HEADS + h];
    const float inv = __frcp_rn(den);
    v.x *= inv; v.y *= inv; v.z *= inv; v.w *= inv;

    float sum = v.x + v.y + v.z + v.w;
    float sq  = v.x * v.x + v.y * v.y + v.z * v.z + v.w * v.w;
#pragma unroll
    for (int o = 16; o; o >>= 1) {
        sum += __shfl_xor_sync(0xffffffffu, sum, o);
        sq  += __shfl_xor_sync(0xffffffffu, sq, o);
    }
    const int half = (t >> 5) & 1;
    if ((t & 31) == 0) { rs[r][half] = sum; rq[r][half] = sq; }
    __syncthreads();
    if (s == 0) {
        const float S = rs[r][0] + rs[r][1];
        const float Q = rq[r][0] + rq[r][1];
        const float m = S * (1.f / HD);
        const float var = Q * (1.f / HD) - m * m;
        mean_s[r] = m;
        rstd_s[r] = rsqrtf(var + 1e-5f);
    }
    __syncthreads();
    const float m   = mean_s[r];
    const float rsd = rstd_s[r];
    const float4 g = ((const float4*)gamma)[s];
    const float4 b = ((const float4*)beta)[s];
    float4 o;
    o.x = (v.x - m) * rsd * g.x + b.x;
    o.y = (v.y - m) * rsd * g.y + b.y;
    o.z = (v.z - m) * rsd * g.z + b.z;
    o.w = (v.w - m) * rsd * g.w + b.w;
    ((float4*)out)[(size_t)n * (HD / 4) + s] = o;
}

// ---------------- launch ----------------------------------------------------
extern "C" void kernel_launch(void* const* d_in, const int* in_sizes, int n_in,
                              void* d_out, int out_size) {
    const float* x      = (const float*)d_in[0];
    const int*   adj    = (const int*)  d_in[1];
    const float* ef     = (const float*)d_in[2];
    const float* W      = (const float*)d_in[3];
    const float* a_src  = (const float*)d_in[4];
    const float* a_dst  = (const float*)d_in[5];
    const float* ep_w   = (const float*)d_in[6];
    const float* ep_b   = (const float*)d_in[7];
    const float* gamma  = (const float*)d_in[8];
    const float* beta   = (const float*)d_in[9];
    float* out = (float*)d_out;

    const int smem_bytes = (int)sizeof(SmemAttn);   // ~83.7 KB
    cudaFuncSetAttribute(k_attn, cudaFuncAttributeMaxDynamicSharedMemorySize,
                         smem_bytes);

    k_proj  <<<NN / 16, 256>>>(x, W);
    k_scores<<<(NN * HEADS) / 256, 256>>>(a_src, a_dst);
    k_attn  <<<dim3(NN / TI, JSPLIT), 256, smem_bytes>>>(ef, adj, ep_w, ep_b);
    k_final <<<NN / 4, 256>>>(gamma, beta, out);
}